// round 1
// baseline (speedup 1.0000x reference)
#include <cuda_runtime.h>

#define NN 50000
#define EE 400000
#define EP (EE + NN)          // 450000 edges incl. self loops
#define H_ 5
#define C_ 64
#define HC 320                // H_*C_
#define ND 128                // node_dim
#define ED 16                 // edge_dim
#define NEG 0.2f
#define NB_SCAN ((NN + 255) / 256)   // 196

// ---------------- scratch (device globals; no allocation allowed) ----------------
__device__ float g_h[(size_t)NN * HC];        // 64 MB  node features per layer [N,H*C]
__device__ float g_act[(size_t)NN * C_];      // activations between layers [N,C]
__device__ float g_loop[(size_t)NN * ED];     // self-loop edge attrs (mean fill)
__device__ float g_sums[(size_t)NN * ED];
__device__ float g_cnt[NN];
__device__ float g_logits[(size_t)EP * H_];   // attention logits [E',H]
__device__ int   g_deg[NN];
__device__ int   g_row[NN + 1];
__device__ int   g_cur[NN];
__device__ int   g_eid[EP];
__device__ int   g_scantmp[NN];
__device__ int   g_bsum[256];

// ---------------- setup kernels ----------------
__global__ void k_zero_init() {
    int i = blockIdx.x * blockDim.x + threadIdx.x;
    if (i < NN * ED) g_sums[i] = 0.f;
    if (i < NN) { g_cnt[i] = 0.f; g_deg[i] = 0; }
}

__global__ void k_loop_count(const int* __restrict__ ei, const float* __restrict__ ea) {
    int t = blockIdx.x * blockDim.x + threadIdx.x;   // one per (edge, j)
    if (t >= EE * ED) return;
    int e = t >> 4, j = t & 15;
    int dst = ei[EE + e];
    atomicAdd(&g_sums[(size_t)dst * ED + j], ea[t]);
    if (j == 0) atomicAdd(&g_cnt[dst], 1.0f);
}

__global__ void k_loop_fin() {
    int i = blockIdx.x * blockDim.x + threadIdx.x;
    if (i >= NN * ED) return;
    float c = fmaxf(g_cnt[i >> 4], 1.0f);
    g_loop[i] = g_sums[i] / c;
}

__global__ void k_deg(const int* __restrict__ ei) {
    int e = blockIdx.x * blockDim.x + threadIdx.x;
    if (e >= EP) return;
    int dst = (e < EE) ? ei[EE + e] : (e - EE);
    atomicAdd(&g_deg[dst], 1);
}

__global__ void k_scan1() {
    __shared__ int s[256];
    int i = blockIdx.x * 256 + threadIdx.x;
    int v = (i < NN) ? g_deg[i] : 0;
    s[threadIdx.x] = v; __syncthreads();
    for (int off = 1; off < 256; off <<= 1) {
        int t = (threadIdx.x >= off) ? s[threadIdx.x - off] : 0;
        __syncthreads();
        s[threadIdx.x] += t;
        __syncthreads();
    }
    if (i < NN) g_scantmp[i] = s[threadIdx.x];           // inclusive within block
    if (threadIdx.x == 255) g_bsum[blockIdx.x] = s[255]; // block total
}

__global__ void k_scan2() {
    __shared__ int s[256];
    int t = threadIdx.x;
    int v = (t < NB_SCAN) ? g_bsum[t] : 0;
    s[t] = v; __syncthreads();
    for (int off = 1; off < 256; off <<= 1) {
        int x = (t >= off) ? s[t - off] : 0;
        __syncthreads();
        s[t] += x;
        __syncthreads();
    }
    g_bsum[t] = s[t] - v;   // exclusive scan of block sums
}

__global__ void k_scan3() {
    int i = blockIdx.x * blockDim.x + threadIdx.x;
    if (i >= NN) return;
    g_row[i + 1] = g_scantmp[i] + g_bsum[i >> 8];
    int rs = (i == 0) ? 0 : (g_scantmp[i - 1] + g_bsum[(i - 1) >> 8]);
    if (i == 0) g_row[0] = 0;
    g_cur[i] = rs;
}

__global__ void k_scatter(const int* __restrict__ ei) {
    int e = blockIdx.x * blockDim.x + threadIdx.x;
    if (e >= EP) return;
    int dst = (e < EE) ? ei[EE + e] : (e - EE);
    int p = atomicAdd(&g_cur[dst], 1);
    g_eid[p] = e;
}

// ---------------- node GEMM: g_h = A @ W + b  (W resident in smem) ----------------
template <int K>
__global__ void k_gemm(const float* __restrict__ A, const float* __restrict__ W,
                       const float* __restrict__ b) {
    extern __shared__ float sm[];
    float* Ws = sm;                 // K*HC
    float* bs = Ws + K * HC;        // HC
    float* As = bs + HC;            // 8*K
    if (A == nullptr) A = g_act;
    int tid = threadIdx.x;          // 320 threads, tid = output column
    for (int i = tid; i < K * HC; i += 320) Ws[i] = W[i];
    if (tid < HC) bs[tid] = b[tid];
    __syncthreads();
    for (int r0 = blockIdx.x * 8; r0 < NN; r0 += gridDim.x * 8) {
        int nr = min(8, NN - r0);
        __syncthreads();
        for (int i = tid; i < nr * K; i += 320) As[i] = A[(size_t)r0 * K + i];
        __syncthreads();
        float acc[8];
#pragma unroll
        for (int r = 0; r < 8; r++) acc[r] = bs[tid];
#pragma unroll 4
        for (int k = 0; k < K; k++) {
            float w = Ws[k * HC + tid];
#pragma unroll
            for (int r = 0; r < 8; r++) acc[r] += As[r * K + k] * w;
        }
#pragma unroll
        for (int r = 0; r < 8; r++)
            if (r < nr) g_h[(size_t)(r0 + r) * HC + tid] = acc[r];
    }
}

// ---------------- edge logits: one warp handles TWO edges ----------------
__global__ void k_logits(const int* __restrict__ ei, const float* __restrict__ eattr,
                         const float* __restrict__ We, const float* __restrict__ att) {
    __shared__ float Wes[ED * HC];   // 20 KB
    __shared__ float atts[HC];
    int tid = threadIdx.x;
    for (int i = tid; i < ED * HC; i += blockDim.x) Wes[i] = We[i];
    for (int i = tid; i < HC; i += blockDim.x) atts[i] = att[i];
    __syncthreads();
    int gw = (blockIdx.x * blockDim.x + tid) >> 5;
    int lane = tid & 31;
    int e0 = gw * 2, e1 = gw * 2 + 1;
    if (e0 >= EP) return;
    bool has1 = (e1 < EP);
    int src0, dst0, src1 = 0, dst1 = 0;
    const float *ea0p, *ea1p = g_loop;
    if (e0 < EE) { src0 = ei[e0]; dst0 = ei[EE + e0]; ea0p = eattr + (size_t)e0 * ED; }
    else         { src0 = dst0 = e0 - EE;             ea0p = g_loop + (size_t)(e0 - EE) * ED; }
    if (has1) {
        if (e1 < EE) { src1 = ei[e1]; dst1 = ei[EE + e1]; ea1p = eattr + (size_t)e1 * ED; }
        else         { src1 = dst1 = e1 - EE;             ea1p = g_loop + (size_t)(e1 - EE) * ED; }
    }
    float ea0[ED], ea1[ED];
#pragma unroll
    for (int j = 0; j < ED; j++) { ea0[j] = ea0p[j]; ea1[j] = has1 ? ea1p[j] : 0.f; }
    const float* hs0 = g_h + (size_t)src0 * HC;
    const float* hd0 = g_h + (size_t)dst0 * HC;
    const float* hs1 = g_h + (size_t)src1 * HC;
    const float* hd1 = g_h + (size_t)dst1 * HC;
#pragma unroll
    for (int hh = 0; hh < H_; hh++) {
        float a0 = 0.f, a1 = 0.f;
#pragma unroll
        for (int k = 0; k < 2; k++) {
            int c = hh * C_ + k * 32 + lane;
            float ec0 = 0.f, ec1 = 0.f;
#pragma unroll
            for (int j = 0; j < ED; j++) {
                float w = Wes[j * HC + c];
                ec0 += ea0[j] * w;
                ec1 += ea1[j] * w;
            }
            float v0 = hs0[c] + hd0[c] + ec0; v0 = (v0 > 0.f) ? v0 : NEG * v0;
            float v1 = hs1[c] + hd1[c] + ec1; v1 = (v1 > 0.f) ? v1 : NEG * v1;
            float aw = atts[c];
            a0 += aw * v0;
            a1 += aw * v1;
        }
#pragma unroll
        for (int off = 16; off; off >>= 1) {
            a0 += __shfl_xor_sync(0xffffffffu, a0, off);
            a1 += __shfl_xor_sync(0xffffffffu, a1, off);
        }
        if (lane == 0) {
            g_logits[(size_t)e0 * H_ + hh] = a0;
            if (has1) g_logits[(size_t)e1 * H_ + hh] = a1;
        }
    }
}

// ---------------- per-dst softmax + aggregation + head-mean + bias + ELU ----------------
__global__ void k_aggregate(const int* __restrict__ ei, const float* __restrict__ bias,
                            float* __restrict__ outp) {
    int warp = (blockIdx.x * blockDim.x + threadIdx.x) >> 5;
    int lane = threadIdx.x & 31;
    if (warp >= NN) return;
    if (outp == nullptr) outp = g_act;
    int n = warp;
    int rs = g_row[n], re = g_row[n + 1];
    float m[H_];
#pragma unroll
    for (int h = 0; h < H_; h++) m[h] = -1e30f;
    for (int p = rs; p < re; p++) {
        int e = g_eid[p];
        const float* lg = &g_logits[(size_t)e * H_];
#pragma unroll
        for (int h = 0; h < H_; h++) m[h] = fmaxf(m[h], lg[h]);
    }
    float den[H_], acc[H_ * 2];
#pragma unroll
    for (int h = 0; h < H_; h++) den[h] = 0.f;
#pragma unroll
    for (int i = 0; i < H_ * 2; i++) acc[i] = 0.f;
    for (int p = rs; p < re; p++) {
        int e = g_eid[p];
        int src = (e < EE) ? ei[e] : (e - EE);
        const float* lg = &g_logits[(size_t)e * H_];
        const float* hs = &g_h[(size_t)src * HC];
#pragma unroll
        for (int h = 0; h < H_; h++) {
            float ex = expf(lg[h] - m[h]);
            den[h] += ex;
            acc[h * 2 + 0] += ex * hs[h * C_ + lane];
            acc[h * 2 + 1] += ex * hs[h * C_ + 32 + lane];
        }
    }
    float o0 = 0.f, o1 = 0.f;
#pragma unroll
    for (int h = 0; h < H_; h++) {
        float inv = 1.f / (den[h] + 1e-16f);
        o0 += acc[h * 2 + 0] * inv;
        o1 += acc[h * 2 + 1] * inv;
    }
    o0 *= (1.f / H_); o1 *= (1.f / H_);
    o0 += bias[lane]; o1 += bias[32 + lane];
    o0 = (o0 > 0.f) ? o0 : expm1f(o0);
    o1 = (o1 > 0.f) ? o1 : expm1f(o1);
    outp[(size_t)n * C_ + lane] = o0;
    outp[(size_t)n * C_ + 32 + lane] = o1;
}

// ---------------- host ----------------
extern "C" void kernel_launch(void* const* d_in, const int* in_sizes, int n_in,
                              void* d_out, int out_size) {
    const float* x      = (const float*)d_in[0];
    const int*   ei     = (const int*)  d_in[1];
    const float* eattr  = (const float*)d_in[2];
    const float* W0     = (const float*)d_in[3];
    const float* b0     = (const float*)d_in[4];
    const float* We0    = (const float*)d_in[5];
    const float* att0   = (const float*)d_in[6];
    const float* bias0  = (const float*)d_in[7];
    const float* W12    = (const float*)d_in[8];
    const float* b12    = (const float*)d_in[9];
    const float* We12   = (const float*)d_in[10];
    const float* att12  = (const float*)d_in[11];
    const float* bias12 = (const float*)d_in[12];
    float* out = (float*)d_out;

    const int SM128 = (128 * HC + HC + 8 * 128) * 4;  // 169216 B
    const int SM64  = (64 * HC + HC + 8 * 64) * 4;    //  85248 B
    cudaFuncSetAttribute(k_gemm<128>, cudaFuncAttributeMaxDynamicSharedMemorySize, SM128);
    cudaFuncSetAttribute(k_gemm<64>,  cudaFuncAttributeMaxDynamicSharedMemorySize, SM64);

    // ---- graph prep (self-loop attrs + CSR by dst) ----
    k_zero_init<<<(NN * ED + 255) / 256, 256>>>();
    k_loop_count<<<(EE * ED + 255) / 256, 256>>>(ei, eattr);
    k_loop_fin<<<(NN * ED + 255) / 256, 256>>>();
    k_deg<<<(EP + 255) / 256, 256>>>(ei);
    k_scan1<<<NB_SCAN, 256>>>();
    k_scan2<<<1, 256>>>();
    k_scan3<<<NB_SCAN, 256>>>();
    k_scatter<<<(EP + 255) / 256, 256>>>(ei);

    const int LOGITS_BLOCKS = (EP / 2 + 7) / 8;   // 2 edges/warp, 8 warps/block
    const int AGG_BLOCKS    = (NN + 7) / 8;       // 1 node/warp, 8 warps/block

    // ---- layer 0 ----
    k_gemm<128><<<148, 320, SM128>>>(x, W0, b0);
    k_logits<<<LOGITS_BLOCKS, 256>>>(ei, eattr, We0, att0);
    k_aggregate<<<AGG_BLOCKS, 256>>>(ei, bias0, nullptr);

    // ---- layers 1, 2 ----
    for (int i = 0; i < 2; i++) {
        k_gemm<64><<<148, 320, SM64>>>(nullptr, W12 + (size_t)i * 64 * HC, b12 + i * HC);
        k_logits<<<LOGITS_BLOCKS, 256>>>(ei, eattr, We12 + (size_t)i * ED * HC, att12 + i * H_ * C_);
        k_aggregate<<<AGG_BLOCKS, 256>>>(ei, bias12 + i * C_, (i == 1) ? out : nullptr);
    }
}